// round 1
// baseline (speedup 1.0000x reference)
#include <cuda_runtime.h>
#include <cuda_bf16.h>

#define NUM_EXPERTS 8
#define TOP_K 2
#define HIDDEN 1024
#define NUM_TOKENS 8192

// ---------------- scratch (allocation-free: __device__ globals) -------------
__device__ int   g_count[NUM_EXPERTS];
__device__ int   g_tok[NUM_EXPERTS * NUM_TOKENS];
__device__ float g_wt [NUM_EXPERTS * NUM_TOKENS];

// ---------------- kernel 1: zero output + counters ---------------------------
__global__ void zero_kernel(float4* out4) {
    int idx = blockIdx.x * blockDim.x + threadIdx.x;
    out4[idx] = make_float4(0.f, 0.f, 0.f, 0.f);
    if (blockIdx.x == 0 && threadIdx.x < NUM_EXPERTS) g_count[threadIdx.x] = 0;
}

// ---------------- kernel 2: gating (logits -> softmax -> top2 -> dispatch) --
__global__ void gate_kernel(const float* __restrict__ x,
                            const float* __restrict__ gw) {
    __shared__ float sg[NUM_EXPERTS * HIDDEN]; // 32 KB
    int tid = threadIdx.x;
    for (int i = tid; i < NUM_EXPERTS * HIDDEN; i += blockDim.x) sg[i] = gw[i];
    __syncthreads();

    int warp = tid >> 5, lane = tid & 31;
    int t = blockIdx.x * (blockDim.x >> 5) + warp;
    if (t >= NUM_TOKENS) return;

    const float* xr = x + (size_t)t * HIDDEN;
    float acc[NUM_EXPERTS];
#pragma unroll
    for (int e = 0; e < NUM_EXPERTS; e++) acc[e] = 0.f;

    for (int i = lane; i < HIDDEN; i += 32) {
        float xv = xr[i];
#pragma unroll
        for (int e = 0; e < NUM_EXPERTS; e++)
            acc[e] = fmaf(xv, sg[e * HIDDEN + i], acc[e]);
    }
#pragma unroll
    for (int e = 0; e < NUM_EXPERTS; e++) {
#pragma unroll
        for (int o = 16; o > 0; o >>= 1)
            acc[e] += __shfl_xor_sync(0xFFFFFFFFu, acc[e], o);
    }

    if (lane == 0) {
        // softmax over 8 logits
        float m = acc[0];
#pragma unroll
        for (int e = 1; e < NUM_EXPERTS; e++) m = fmaxf(m, acc[e]);
        float p[NUM_EXPERTS], s = 0.f;
#pragma unroll
        for (int e = 0; e < NUM_EXPERTS; e++) { p[e] = __expf(acc[e] - m); s += p[e]; }
        float inv = 1.f / s;
#pragma unroll
        for (int e = 0; e < NUM_EXPERTS; e++) p[e] *= inv;

        // top-2, lowest index wins ties (strict > scan) — matches jax.lax.top_k
        int i1 = 0;
#pragma unroll
        for (int e = 1; e < NUM_EXPERTS; e++) if (p[e] > p[i1]) i1 = e;
        int i2 = (i1 == 0) ? 1 : 0;
#pragma unroll
        for (int e = 0; e < NUM_EXPERTS; e++)
            if (e != i1 && p[e] > p[i2]) i2 = e;

        int pos1 = atomicAdd(&g_count[i1], 1);
        g_tok[i1 * NUM_TOKENS + pos1] = t;
        g_wt [i1 * NUM_TOKENS + pos1] = p[i1];
        int pos2 = atomicAdd(&g_count[i2], 1);
        g_tok[i2 * NUM_TOKENS + pos2] = t;
        g_wt [i2 * NUM_TOKENS + pos2] = p[i2];
    }
}

// ---------------- kernel 3: grouped expert GEMM ------------------------------
// per expert e, for tokens in its list: out[tok] += (w * x[tok]) @ W_e^T
// tile: BM=64 tokens, BN=64 out-dims, BK=16; 256 threads, 4x4 per thread
#define BM 64
#define BN 64
#define BK 16
#define LDS_STRIDE 68   // 16B-aligned rows, limits STS conflicts to 2-way

__global__ __launch_bounds__(256) void moe_gemm_kernel(
    const float* __restrict__ x,
    const float* __restrict__ ew,
    float* __restrict__ out) {
    int e = blockIdx.z;
    int cnt = g_count[e];
    int m0 = blockIdx.y * BM;
    if (m0 >= cnt) return;
    int n0 = blockIdx.x * BN;

    __shared__ float As[BK][LDS_STRIDE];
    __shared__ float Bs[BK][LDS_STRIDE];

    int tid = threadIdx.x;

    // load mapping: thread -> (row lm in tile, 4 consecutive k at lk4)
    int lm  = tid >> 2;          // 0..63
    int lk4 = (tid & 3) * 4;     // 0,4,8,12

    int   m = m0 + lm;
    int   tok = 0;
    float w = 0.f;
    bool  mvalid = (m < cnt);
    if (mvalid) {
        tok = g_tok[e * NUM_TOKENS + m];
        w   = g_wt [e * NUM_TOKENS + m];
    }
    const float* arow = x + (size_t)tok * HIDDEN;                 // token row
    const float* brow = ew + ((size_t)e * HIDDEN + n0 + lm) * HIDDEN; // W_e row

    // compute mapping: 16x16 thread grid, 4x4 micro-tile
    int tm = (tid & 15) * 4;
    int tn = (tid >> 4) * 4;

    float acc[4][4];
#pragma unroll
    for (int i = 0; i < 4; i++)
#pragma unroll
        for (int j = 0; j < 4; j++) acc[i][j] = 0.f;

    for (int k0 = 0; k0 < HIDDEN; k0 += BK) {
        float4 av = make_float4(0.f, 0.f, 0.f, 0.f);
        if (mvalid) {
            av = *reinterpret_cast<const float4*>(arow + k0 + lk4);
            av.x *= w; av.y *= w; av.z *= w; av.w *= w;   // fold routing weight
        }
        float4 bv = *reinterpret_cast<const float4*>(brow + k0 + lk4);

        __syncthreads();
        As[lk4 + 0][lm] = av.x; As[lk4 + 1][lm] = av.y;
        As[lk4 + 2][lm] = av.z; As[lk4 + 3][lm] = av.w;
        Bs[lk4 + 0][lm] = bv.x; Bs[lk4 + 1][lm] = bv.y;
        Bs[lk4 + 2][lm] = bv.z; Bs[lk4 + 3][lm] = bv.w;
        __syncthreads();

#pragma unroll
        for (int k = 0; k < BK; k++) {
            float4 a = *reinterpret_cast<const float4*>(&As[k][tm]);
            float4 b = *reinterpret_cast<const float4*>(&Bs[k][tn]);
            float ar[4] = {a.x, a.y, a.z, a.w};
            float br[4] = {b.x, b.y, b.z, b.w};
#pragma unroll
            for (int i = 0; i < 4; i++)
#pragma unroll
                for (int j = 0; j < 4; j++)
                    acc[i][j] = fmaf(ar[i], br[j], acc[i][j]);
        }
    }

    // scatter-add (each out element receives exactly 2 contributions onto 0)
#pragma unroll
    for (int i = 0; i < 4; i++) {
        int mm = m0 + tm + i;
        if (mm < cnt) {
            int t2 = g_tok[e * NUM_TOKENS + mm];
            float* orow = out + (size_t)t2 * HIDDEN + n0 + tn;
#pragma unroll
            for (int j = 0; j < 4; j++)
                atomicAdd(&orow[j], acc[i][j]);
        }
    }
}

// ---------------- launch ------------------------------------------------------
extern "C" void kernel_launch(void* const* d_in, const int* in_sizes, int n_in,
                              void* d_out, int out_size) {
    const float* x  = (const float*)d_in[0];   // [8192,1024]
    const float* gw = (const float*)d_in[1];   // [8,1024]
    const float* ew = (const float*)d_in[2];   // [8,1024,1024]
    float* out = (float*)d_out;                // [8192,1024]

    // zero: 8192*1024 floats = 2,097,152 float4 = 8192 blocks * 256 threads
    zero_kernel<<<(NUM_TOKENS * HIDDEN / 4 + 255) / 256, 256>>>((float4*)out);

    // gating: 8 warps/block -> 1024 blocks
    gate_kernel<<<NUM_TOKENS / 8, 256>>>(x, gw);

    // grouped GEMM: (N tiles, M tiles upper bound, experts)
    dim3 grid(HIDDEN / BN, (NUM_TOKENS + BM - 1) / BM, NUM_EXPERTS);
    moe_gemm_kernel<<<grid, 256>>>(x, ew, out);
}

// round 3
// speedup vs baseline: 2.0134x; 2.0134x over previous
#include <cuda_runtime.h>
#include <cuda_bf16.h>
#include <cstdint>

#define NUM_EXPERTS 8
#define HIDDEN 1024
#define NUM_TOKENS 8192

// ---------------- scratch (allocation-free: __device__ globals) -------------
__device__ int   g_count[NUM_EXPERTS];
__device__ int   g_tok[NUM_EXPERTS * NUM_TOKENS];
__device__ float g_wt [NUM_EXPERTS * NUM_TOKENS];

// ---------------- helpers ----------------------------------------------------
__device__ __forceinline__ uint32_t smem_u32(const void* p) {
    uint32_t a;
    asm("{ .reg .u64 t; cvta.to.shared.u64 t, %1; cvt.u32.u64 %0, t; }"
        : "=r"(a) : "l"(p));
    return a;
}

__device__ __forceinline__ void ldsm4(uint32_t& r0, uint32_t& r1, uint32_t& r2,
                                      uint32_t& r3, uint32_t addr) {
    asm volatile("ldmatrix.sync.aligned.m8n8.x4.shared.b16 {%0,%1,%2,%3}, [%4];"
                 : "=r"(r0), "=r"(r1), "=r"(r2), "=r"(r3) : "r"(addr));
}

__device__ __forceinline__ void mma16816(float* c, const uint32_t* a,
                                         uint32_t b0, uint32_t b1) {
    asm volatile(
        "mma.sync.aligned.m16n8k16.row.col.f32.bf16.bf16.f32 "
        "{%0,%1,%2,%3}, {%4,%5,%6,%7}, {%8,%9}, {%0,%1,%2,%3};"
        : "+f"(c[0]), "+f"(c[1]), "+f"(c[2]), "+f"(c[3])
        : "r"(a[0]), "r"(a[1]), "r"(a[2]), "r"(a[3]), "r"(b0), "r"(b1));
}

__device__ __forceinline__ void split2(float a, float b, uint32_t& hi, uint32_t& lo) {
    __nv_bfloat16 ha = __float2bfloat16_rn(a);
    __nv_bfloat16 hb = __float2bfloat16_rn(b);
    __nv_bfloat16 la = __float2bfloat16_rn(a - __bfloat162float(ha));
    __nv_bfloat16 lb = __float2bfloat16_rn(b - __bfloat162float(hb));
    __nv_bfloat162 h; h.x = ha; h.y = hb;
    __nv_bfloat162 l; l.x = la; l.y = lb;
    hi = *reinterpret_cast<uint32_t*>(&h);
    lo = *reinterpret_cast<uint32_t*>(&l);
}

// ---------------- kernel 1: zero output + counters ---------------------------
__global__ void zero_kernel(float4* out4) {
    int idx = blockIdx.x * blockDim.x + threadIdx.x;
    out4[idx] = make_float4(0.f, 0.f, 0.f, 0.f);
    if (blockIdx.x == 0 && threadIdx.x < NUM_EXPERTS) g_count[threadIdx.x] = 0;
}

// ---------------- kernel 2: gating ------------------------------------------
__global__ void gate_kernel(const float* __restrict__ x,
                            const float* __restrict__ gw) {
    __shared__ float sg[NUM_EXPERTS * HIDDEN]; // 32 KB
    int tid = threadIdx.x;
    for (int i = tid; i < NUM_EXPERTS * HIDDEN; i += blockDim.x) sg[i] = gw[i];
    __syncthreads();

    int warp = tid >> 5, lane = tid & 31;
    int t = blockIdx.x * (blockDim.x >> 5) + warp;
    if (t >= NUM_TOKENS) return;

    const float* xr = x + (size_t)t * HIDDEN;
    float acc[NUM_EXPERTS];
#pragma unroll
    for (int e = 0; e < NUM_EXPERTS; e++) acc[e] = 0.f;

    for (int i = lane; i < HIDDEN; i += 32) {
        float xv = xr[i];
#pragma unroll
        for (int e = 0; e < NUM_EXPERTS; e++)
            acc[e] = fmaf(xv, sg[e * HIDDEN + i], acc[e]);
    }
#pragma unroll
    for (int e = 0; e < NUM_EXPERTS; e++) {
#pragma unroll
        for (int o = 16; o > 0; o >>= 1)
            acc[e] += __shfl_xor_sync(0xFFFFFFFFu, acc[e], o);
    }

    if (lane == 0) {
        float m = acc[0];
#pragma unroll
        for (int e = 1; e < NUM_EXPERTS; e++) m = fmaxf(m, acc[e]);
        float p[NUM_EXPERTS], s = 0.f;
#pragma unroll
        for (int e = 0; e < NUM_EXPERTS; e++) { p[e] = __expf(acc[e] - m); s += p[e]; }
        float inv = 1.f / s;
#pragma unroll
        for (int e = 0; e < NUM_EXPERTS; e++) p[e] *= inv;

        int i1 = 0;
#pragma unroll
        for (int e = 1; e < NUM_EXPERTS; e++) if (p[e] > p[i1]) i1 = e;
        int i2 = (i1 == 0) ? 1 : 0;
#pragma unroll
        for (int e = 0; e < NUM_EXPERTS; e++)
            if (e != i1 && p[e] > p[i2]) i2 = e;

        int pos1 = atomicAdd(&g_count[i1], 1);
        g_tok[i1 * NUM_TOKENS + pos1] = t;
        g_wt [i1 * NUM_TOKENS + pos1] = p[i1];
        int pos2 = atomicAdd(&g_count[i2], 1);
        g_tok[i2 * NUM_TOKENS + pos2] = t;
        g_wt [i2 * NUM_TOKENS + pos2] = p[i2];
    }
}

// ---------------- kernel 3: HMMA grouped GEMM (bf16x3 split) ----------------
// CTA: 128 tokens x 128 N, BK=32. 8 warps in 2(M) x 4(N).
// smem rows padded to 40 bf16 (80 B) -> conflict-free ldmatrix/STS.
#define BK   32
#define LDK  40
#define ROWB (LDK * 2)         // 80 bytes per row
#define SM_AH 0
#define SM_AL (128 * ROWB)     // 10240
#define SM_BH (2 * 128 * ROWB) // 20480
#define SM_BL (3 * 128 * ROWB) // 30720
#define SM_TOT (4 * 128 * ROWB)

__global__ __launch_bounds__(256, 2) void moe_hmma_kernel(
    const float* __restrict__ x,
    const float* __restrict__ ew,
    float* __restrict__ out) {
    int e = blockIdx.z;
    int cnt = g_count[e];
    int m0 = blockIdx.y * 128;
    if (m0 >= cnt) return;
    int n0 = blockIdx.x * 128;

    __shared__ __align__(16) char sm[SM_TOT];
    __shared__ int   s_tok[128];
    __shared__ float s_wgt[128];

    int tid = threadIdx.x, wid = tid >> 5, lane = tid & 31;
    uint32_t sb = smem_u32(sm);

    if (tid < 128) {
        int m = m0 + tid;
        int tok = -1; float wv = 0.f;
        if (m < cnt) {
            tok = g_tok[e * NUM_TOKENS + m];
            wv  = g_wt [e * NUM_TOKENS + m];
        }
        s_tok[tid] = tok;
        s_wgt[tid] = wv;
    }
    __syncthreads();

    // ---- loader mapping: 256 threads -> 128 A rows + 128 B rows -------------
    int  row = tid & 127;
    bool isB = (tid >= 128);
    const float* grow;
    float wfold;
    if (isB) {
        grow  = ew + ((size_t)e * HIDDEN + n0 + row) * HIDDEN;
        wfold = 1.f;
    } else {
        int tok = s_tok[row];
        wfold   = s_wgt[row];                 // 0 for padding rows -> zeros
        grow    = x + (size_t)(tok >= 0 ? tok : 0) * HIDDEN;
    }
    uint32_t sts_hi = sb + (isB ? SM_BH : SM_AH) + row * ROWB;

    // ---- compute mapping -----------------------------------------------------
    int warp_m = wid & 1;        // 0..1 (64 rows each)
    int warp_n = wid >> 1;       // 0..3 (32 cols each)

    // ldmatrix lane offsets (bytes)
    uint32_t a_lane_off = (uint32_t)((lane & 15) * ROWB + (lane >> 4) * 16);
    uint32_t b_lane_off = (uint32_t)((((lane >> 4) * 8) + (lane & 7)) * ROWB
                                     + ((lane >> 3) & 1) * 16);
    uint32_t aH = sb + SM_AH + warp_m * 64 * ROWB + a_lane_off;
    uint32_t aL = sb + SM_AL + warp_m * 64 * ROWB + a_lane_off;
    uint32_t bH = sb + SM_BH + warp_n * 32 * ROWB + b_lane_off;
    uint32_t bL = sb + SM_BL + warp_n * 32 * ROWB + b_lane_off;

    float acc[4][4][4];
#pragma unroll
    for (int i = 0; i < 4; i++)
#pragma unroll
        for (int j = 0; j < 4; j++)
#pragma unroll
            for (int q = 0; q < 4; q++) acc[i][j][q] = 0.f;

    for (int c = 0; c < HIDDEN / BK; c++) {
        // ---- stage fp32 -> split bf16 hi/lo into smem ------------------------
        const float4* gsrc = reinterpret_cast<const float4*>(grow + c * BK);
#pragma unroll
        for (int g = 0; g < 4; g++) {
            float4 v0 = gsrc[2 * g];
            float4 v1 = gsrc[2 * g + 1];
            v0.x *= wfold; v0.y *= wfold; v0.z *= wfold; v0.w *= wfold;
            v1.x *= wfold; v1.y *= wfold; v1.z *= wfold; v1.w *= wfold;
            uint4 H, L;
            split2(v0.x, v0.y, H.x, L.x);
            split2(v0.z, v0.w, H.y, L.y);
            split2(v1.x, v1.y, H.z, L.z);
            split2(v1.z, v1.w, H.w, L.w);
            *reinterpret_cast<uint4*>((char*)sm + (sts_hi - sb) + g * 16) = H;
            *reinterpret_cast<uint4*>((char*)sm + (sts_hi - sb) + SM_AL + g * 16) = L;
        }
        __syncthreads();

        // ---- 2 k-steps of 16 -------------------------------------------------
#pragma unroll
        for (int ks = 0; ks < 2; ks++) {
            uint32_t ko = (uint32_t)(ks * 32);  // 16 bf16 = 32 B

            uint32_t ah[4][4], bh[2][4];
#pragma unroll
            for (int mf = 0; mf < 4; mf++)
                ldsm4(ah[mf][0], ah[mf][1], ah[mf][2], ah[mf][3],
                      aH + mf * 16 * ROWB + ko);
#pragma unroll
            for (int bf = 0; bf < 2; bf++)
                ldsm4(bh[bf][0], bh[bf][1], bh[bf][2], bh[bf][3],
                      bH + bf * 16 * ROWB + ko);

            // term 1: ah * bh
#pragma unroll
            for (int mf = 0; mf < 4; mf++)
#pragma unroll
                for (int nf = 0; nf < 4; nf++)
                    mma16816(acc[mf][nf], ah[mf],
                             bh[nf >> 1][(nf & 1) * 2], bh[nf >> 1][(nf & 1) * 2 + 1]);

            // term 2: al * bh
            {
                uint32_t al[4][4];
#pragma unroll
                for (int mf = 0; mf < 4; mf++)
                    ldsm4(al[mf][0], al[mf][1], al[mf][2], al[mf][3],
                          aL + mf * 16 * ROWB + ko);
#pragma unroll
                for (int mf = 0; mf < 4; mf++)
#pragma unroll
                    for (int nf = 0; nf < 4; nf++)
                        mma16816(acc[mf][nf], al[mf],
                                 bh[nf >> 1][(nf & 1) * 2], bh[nf >> 1][(nf & 1) * 2 + 1]);
            }

            // term 3: ah * bl
            {
                uint32_t bl[2][4];
#pragma unroll
                for (int bf = 0; bf < 2; bf++)
                    ldsm4(bl[bf][0], bl[bf][1], bl[bf][2], bl[bf][3],
                          bL + bf * 16 * ROWB + ko);
#pragma unroll
                for (int mf = 0; mf < 4; mf++)
#pragma unroll
                    for (int nf = 0; nf < 4; nf++)
                        mma16816(acc[mf][nf], ah[mf],
                                 bl[nf >> 1][(nf & 1) * 2], bl[nf >> 1][(nf & 1) * 2 + 1]);
            }
        }
        __syncthreads();
    }

    // ---- epilogue: fragment-direct atomic scatter (weight already folded) ---
    int tq  = lane >> 2;
    int tc2 = (lane & 3) * 2;
#pragma unroll
    for (int mf = 0; mf < 4; mf++) {
        int r0 = warp_m * 64 + mf * 16 + tq;
        int t0 = s_tok[r0];
        int t1 = s_tok[r0 + 8];
        float* o0 = (t0 >= 0) ? out + (size_t)t0 * HIDDEN : nullptr;
        float* o1 = (t1 >= 0) ? out + (size_t)t1 * HIDDEN : nullptr;
#pragma unroll
        for (int nf = 0; nf < 4; nf++) {
            int col = n0 + warp_n * 32 + nf * 8 + tc2;
            if (o0) {
                atomicAdd(o0 + col,     acc[mf][nf][0]);
                atomicAdd(o0 + col + 1, acc[mf][nf][1]);
            }
            if (o1) {
                atomicAdd(o1 + col,     acc[mf][nf][2]);
                atomicAdd(o1 + col + 1, acc[mf][nf][3]);
            }
        }
    }
}

// ---------------- launch ------------------------------------------------------
extern "C" void kernel_launch(void* const* d_in, const int* in_sizes, int n_in,
                              void* d_out, int out_size) {
    const float* x  = (const float*)d_in[0];   // [8192,1024]
    const float* gw = (const float*)d_in[1];   // [8,1024]
    const float* ew = (const float*)d_in[2];   // [8,1024,1024]
    float* out = (float*)d_out;                // [8192,1024]

    zero_kernel<<<(NUM_TOKENS * HIDDEN / 4 + 255) / 256, 256>>>((float4*)out);
    gate_kernel<<<NUM_TOKENS / 8, 256>>>(x, gw);

    dim3 grid(HIDDEN / 128, NUM_TOKENS / 128, NUM_EXPERTS);
    moe_hmma_kernel<<<grid, 256>>>(x, ew, out);
}

// round 4
// speedup vs baseline: 2.3081x; 1.1464x over previous
#include <cuda_runtime.h>
#include <cuda_bf16.h>
#include <cstdint>

#define NUM_EXPERTS 8
#define HIDDEN 1024
#define NUM_TOKENS 8192

// ---------------- scratch (allocation-free: __device__ globals) -------------
__device__ int   g_count[NUM_EXPERTS];
__device__ int   g_tok[NUM_EXPERTS * NUM_TOKENS];
__device__ float g_wt [NUM_EXPERTS * NUM_TOKENS];
__device__ __nv_bfloat16 g_xh [NUM_TOKENS * HIDDEN];
__device__ __nv_bfloat16 g_xl [NUM_TOKENS * HIDDEN];
__device__ __nv_bfloat16 g_ewh[NUM_EXPERTS * HIDDEN * HIDDEN];
__device__ __nv_bfloat16 g_ewl[NUM_EXPERTS * HIDDEN * HIDDEN];

// ---------------- helpers ----------------------------------------------------
__device__ __forceinline__ uint32_t smem_u32(const void* p) {
    uint32_t a;
    asm("{ .reg .u64 t; cvta.to.shared.u64 t, %1; cvt.u32.u64 %0, t; }"
        : "=r"(a) : "l"(p));
    return a;
}

__device__ __forceinline__ void cp16(uint32_t dst, const void* src) {
    asm volatile("cp.async.cg.shared.global [%0], [%1], 16;"
                 :: "r"(dst), "l"(src) : "memory");
}
__device__ __forceinline__ void cp_commit() {
    asm volatile("cp.async.commit_group;" ::: "memory");
}
template <int N>
__device__ __forceinline__ void cp_wait() {
    asm volatile("cp.async.wait_group %0;" :: "n"(N) : "memory");
}

__device__ __forceinline__ void ldsm4(uint32_t& r0, uint32_t& r1, uint32_t& r2,
                                      uint32_t& r3, uint32_t addr) {
    asm volatile("ldmatrix.sync.aligned.m8n8.x4.shared.b16 {%0,%1,%2,%3}, [%4];"
                 : "=r"(r0), "=r"(r1), "=r"(r2), "=r"(r3) : "r"(addr));
}

__device__ __forceinline__ void mma16816(float* c, const uint32_t* a,
                                         uint32_t b0, uint32_t b1) {
    asm volatile(
        "mma.sync.aligned.m16n8k16.row.col.f32.bf16.bf16.f32 "
        "{%0,%1,%2,%3}, {%4,%5,%6,%7}, {%8,%9}, {%0,%1,%2,%3};"
        : "+f"(c[0]), "+f"(c[1]), "+f"(c[2]), "+f"(c[3])
        : "r"(a[0]), "r"(a[1]), "r"(a[2]), "r"(a[3]), "r"(b0), "r"(b1));
}

__device__ __forceinline__ void split2(float a, float b, uint32_t& hi, uint32_t& lo) {
    __nv_bfloat16 ha = __float2bfloat16_rn(a);
    __nv_bfloat16 hb = __float2bfloat16_rn(b);
    __nv_bfloat16 la = __float2bfloat16_rn(a - __bfloat162float(ha));
    __nv_bfloat16 lb = __float2bfloat16_rn(b - __bfloat162float(hb));
    __nv_bfloat162 h; h.x = ha; h.y = hb;
    __nv_bfloat162 l; l.x = la; l.y = lb;
    hi = *reinterpret_cast<uint32_t*>(&h);
    lo = *reinterpret_cast<uint32_t*>(&l);
}

// ---------------- kernel 1: zero output + counters ---------------------------
__global__ void zero_kernel(float4* out4) {
    int idx = blockIdx.x * blockDim.x + threadIdx.x;
    out4[idx] = make_float4(0.f, 0.f, 0.f, 0.f);
    if (blockIdx.x == 0 && threadIdx.x < NUM_EXPERTS) g_count[threadIdx.x] = 0;
}

// ---------------- kernel 1b: fp32 -> bf16 hi/lo pre-conversion ---------------
#define XQ (NUM_TOKENS * HIDDEN / 4)
#define EQ (NUM_EXPERTS * HIDDEN * HIDDEN / 4)
__global__ void convert_kernel(const float4* __restrict__ x4,
                               const float4* __restrict__ ew4) {
    int idx = blockIdx.x * blockDim.x + threadIdx.x;
    float4 v;
    __nv_bfloat16 *h, *l;
    if (idx < XQ) {
        v = x4[idx];
        h = g_xh + (size_t)idx * 4;
        l = g_xl + (size_t)idx * 4;
    } else {
        int j = idx - XQ;
        v = ew4[j];
        h = g_ewh + (size_t)j * 4;
        l = g_ewl + (size_t)j * 4;
    }
    uint2 H, L;
    split2(v.x, v.y, H.x, L.x);
    split2(v.z, v.w, H.y, L.y);
    *reinterpret_cast<uint2*>(h) = H;
    *reinterpret_cast<uint2*>(l) = L;
}

// ---------------- kernel 2: gating ------------------------------------------
__global__ void gate_kernel(const float* __restrict__ x,
                            const float* __restrict__ gw) {
    __shared__ float sg[NUM_EXPERTS * HIDDEN]; // 32 KB
    int tid = threadIdx.x;
    for (int i = tid; i < NUM_EXPERTS * HIDDEN; i += blockDim.x) sg[i] = gw[i];
    __syncthreads();

    int warp = tid >> 5, lane = tid & 31;
    int t = blockIdx.x * (blockDim.x >> 5) + warp;
    if (t >= NUM_TOKENS) return;

    const float* xr = x + (size_t)t * HIDDEN;
    float acc[NUM_EXPERTS];
#pragma unroll
    for (int e = 0; e < NUM_EXPERTS; e++) acc[e] = 0.f;

    for (int i = lane; i < HIDDEN; i += 32) {
        float xv = xr[i];
#pragma unroll
        for (int e = 0; e < NUM_EXPERTS; e++)
            acc[e] = fmaf(xv, sg[e * HIDDEN + i], acc[e]);
    }
#pragma unroll
    for (int e = 0; e < NUM_EXPERTS; e++) {
#pragma unroll
        for (int o = 16; o > 0; o >>= 1)
            acc[e] += __shfl_xor_sync(0xFFFFFFFFu, acc[e], o);
    }

    if (lane == 0) {
        float m = acc[0];
#pragma unroll
        for (int e = 1; e < NUM_EXPERTS; e++) m = fmaxf(m, acc[e]);
        float p[NUM_EXPERTS], s = 0.f;
#pragma unroll
        for (int e = 0; e < NUM_EXPERTS; e++) { p[e] = __expf(acc[e] - m); s += p[e]; }
        float inv = 1.f / s;
#pragma unroll
        for (int e = 0; e < NUM_EXPERTS; e++) p[e] *= inv;

        int i1 = 0;
#pragma unroll
        for (int e = 1; e < NUM_EXPERTS; e++) if (p[e] > p[i1]) i1 = e;
        int i2 = (i1 == 0) ? 1 : 0;
#pragma unroll
        for (int e = 0; e < NUM_EXPERTS; e++)
            if (e != i1 && p[e] > p[i2]) i2 = e;

        int pos1 = atomicAdd(&g_count[i1], 1);
        g_tok[i1 * NUM_TOKENS + pos1] = t;
        g_wt [i1 * NUM_TOKENS + pos1] = p[i1];
        int pos2 = atomicAdd(&g_count[i2], 1);
        g_tok[i2 * NUM_TOKENS + pos2] = t;
        g_wt [i2 * NUM_TOKENS + pos2] = p[i2];
    }
}

// ---------------- kernel 3: HMMA grouped GEMM, cp.async double-buffered -----
// CTA: 128 tokens x 128 N, BK=32. 8 warps in 2(M) x 4(N).
// smem rows padded to 40 bf16 (80 B) -> conflict-free ldmatrix/cp.async.
#define BK   32
#define NC   (HIDDEN / BK)     // 32 chunks
#define ROWB 80
#define OFF_LO 10240           // hi -> lo within a side
#define OFF_B  20480           // A side -> B side
#define STG  40960             // bytes per stage
#define SMEM_DYN (2 * STG)     // 81920

__global__ __launch_bounds__(256, 2) void moe_hmma_kernel(float* __restrict__ out) {
    int e = blockIdx.z;
    int cnt = g_count[e];
    int m0 = blockIdx.y * 128;
    if (m0 >= cnt) return;
    int n0 = blockIdx.x * 128;

    extern __shared__ __align__(16) char sm[];
    __shared__ int   s_tok[128];
    __shared__ float s_wgt[128];

    int tid = threadIdx.x, wid = tid >> 5, lane = tid & 31;
    uint32_t sb = smem_u32(sm);

    if (tid < 128) {
        int m = m0 + tid;
        int tok = -1; float wv = 0.f;
        if (m < cnt) {
            tok = g_tok[e * NUM_TOKENS + m];
            wv  = g_wt [e * NUM_TOKENS + m];
        }
        s_tok[tid] = tok;
        s_wgt[tid] = wv;
    }
    __syncthreads();

    // ---- loader mapping: 256 threads -> 128 A rows + 128 B rows -------------
    int  row = tid & 127;
    bool isB = (tid >= 128);
    const __nv_bfloat16 *hrow, *lrow;
    if (isB) {
        size_t o = ((size_t)e * HIDDEN + n0 + row) * HIDDEN;
        hrow = g_ewh + o;
        lrow = g_ewl + o;
    } else {
        int tok = s_tok[row];
        size_t o = (size_t)(tok >= 0 ? tok : 0) * HIDDEN;
        hrow = g_xh + o;
        lrow = g_xl + o;
    }
    uint32_t dst0 = sb + (isB ? OFF_B : 0) + (uint32_t)row * ROWB;

    // ---- compute mapping -----------------------------------------------------
    int warp_m = wid & 1;        // 0..1 (64 rows each)
    int warp_n = wid >> 1;       // 0..3 (32 cols each)

    uint32_t a_lane_off = (uint32_t)((lane & 15) * ROWB + (lane >> 4) * 16)
                        + (uint32_t)(warp_m * 64 * ROWB);
    uint32_t b_lane_off = (uint32_t)((((lane >> 4) * 8) + (lane & 7)) * ROWB
                                     + ((lane >> 3) & 1) * 16)
                        + OFF_B + (uint32_t)(warp_n * 32 * ROWB);

    float acc[4][4][4];
#pragma unroll
    for (int i = 0; i < 4; i++)
#pragma unroll
        for (int j = 0; j < 4; j++)
#pragma unroll
            for (int q = 0; q < 4; q++) acc[i][j][q] = 0.f;

    // ---- prologue: stage chunk 0 ---------------------------------------------
    {
        const __nv_bfloat16* hp = hrow;
        const __nv_bfloat16* lp = lrow;
#pragma unroll
        for (int j = 0; j < 4; j++) cp16(dst0 + j * 16, hp + j * 8);
#pragma unroll
        for (int j = 0; j < 4; j++) cp16(dst0 + OFF_LO + j * 16, lp + j * 8);
        cp_commit();
    }

    for (int c = 0; c < NC; c++) {
        int s = c & 1;
        if (c + 1 < NC) {
            uint32_t d = dst0 + (uint32_t)((s ^ 1) * STG);
            const __nv_bfloat16* hp = hrow + (c + 1) * BK;
            const __nv_bfloat16* lp = lrow + (c + 1) * BK;
#pragma unroll
            for (int j = 0; j < 4; j++) cp16(d + j * 16, hp + j * 8);
#pragma unroll
            for (int j = 0; j < 4; j++) cp16(d + OFF_LO + j * 16, lp + j * 8);
            cp_commit();
            cp_wait<1>();
        } else {
            cp_wait<0>();
        }
        __syncthreads();

        uint32_t stb = sb + (uint32_t)(s * STG);
        uint32_t aH = stb + a_lane_off;
        uint32_t bH = stb + b_lane_off;

#pragma unroll
        for (int ks = 0; ks < 2; ks++) {
            uint32_t ko = (uint32_t)(ks * 32);  // 16 bf16 = 32 B

            uint32_t ah[4][4], bh[2][4];
#pragma unroll
            for (int mf = 0; mf < 4; mf++)
                ldsm4(ah[mf][0], ah[mf][1], ah[mf][2], ah[mf][3],
                      aH + mf * 16 * ROWB + ko);
#pragma unroll
            for (int bf = 0; bf < 2; bf++)
                ldsm4(bh[bf][0], bh[bf][1], bh[bf][2], bh[bf][3],
                      bH + bf * 16 * ROWB + ko);

            // term 1: ah * bh
#pragma unroll
            for (int mf = 0; mf < 4; mf++)
#pragma unroll
                for (int nf = 0; nf < 4; nf++)
                    mma16816(acc[mf][nf], ah[mf],
                             bh[nf >> 1][(nf & 1) * 2], bh[nf >> 1][(nf & 1) * 2 + 1]);

            // term 2: al * bh
            {
                uint32_t al[4][4];
#pragma unroll
                for (int mf = 0; mf < 4; mf++)
                    ldsm4(al[mf][0], al[mf][1], al[mf][2], al[mf][3],
                          aH + OFF_LO + mf * 16 * ROWB + ko);
#pragma unroll
                for (int mf = 0; mf < 4; mf++)
#pragma unroll
                    for (int nf = 0; nf < 4; nf++)
                        mma16816(acc[mf][nf], al[mf],
                                 bh[nf >> 1][(nf & 1) * 2], bh[nf >> 1][(nf & 1) * 2 + 1]);
            }

            // term 3: ah * bl
            {
                uint32_t bl[2][4];
#pragma unroll
                for (int bf = 0; bf < 2; bf++)
                    ldsm4(bl[bf][0], bl[bf][1], bl[bf][2], bl[bf][3],
                          bH + OFF_LO + bf * 16 * ROWB + ko);
#pragma unroll
                for (int mf = 0; mf < 4; mf++)
#pragma unroll
                    for (int nf = 0; nf < 4; nf++)
                        mma16816(acc[mf][nf], ah[mf],
                                 bl[nf >> 1][(nf & 1) * 2], bl[nf >> 1][(nf & 1) * 2 + 1]);
            }
        }
        __syncthreads();
    }

    // ---- epilogue: weight-scaled float2 atomic scatter ------------------------
    int tq  = lane >> 2;
    int tc2 = (lane & 3) * 2;
#pragma unroll
    for (int mf = 0; mf < 4; mf++) {
        int r0 = warp_m * 64 + mf * 16 + tq;
        int t0 = s_tok[r0];
        int t1 = s_tok[r0 + 8];
        float w0 = s_wgt[r0];
        float w1 = s_wgt[r0 + 8];
        float* o0 = (t0 >= 0) ? out + (size_t)t0 * HIDDEN : nullptr;
        float* o1 = (t1 >= 0) ? out + (size_t)t1 * HIDDEN : nullptr;
#pragma unroll
        for (int nf = 0; nf < 4; nf++) {
            int col = n0 + warp_n * 32 + nf * 8 + tc2;
            if (o0)
                atomicAdd(reinterpret_cast<float2*>(o0 + col),
                          make_float2(w0 * acc[mf][nf][0], w0 * acc[mf][nf][1]));
            if (o1)
                atomicAdd(reinterpret_cast<float2*>(o1 + col),
                          make_float2(w1 * acc[mf][nf][2], w1 * acc[mf][nf][3]));
        }
    }
}

// ---------------- launch ------------------------------------------------------
extern "C" void kernel_launch(void* const* d_in, const int* in_sizes, int n_in,
                              void* d_out, int out_size) {
    const float* x  = (const float*)d_in[0];   // [8192,1024]
    const float* gw = (const float*)d_in[1];   // [8,1024]
    const float* ew = (const float*)d_in[2];   // [8,1024,1024]
    float* out = (float*)d_out;                // [8192,1024]

    cudaFuncSetAttribute(moe_hmma_kernel,
                         cudaFuncAttributeMaxDynamicSharedMemorySize, SMEM_DYN);

    zero_kernel<<<(NUM_TOKENS * HIDDEN / 4 + 255) / 256, 256>>>((float4*)out);
    convert_kernel<<<(XQ + EQ) / 256, 256>>>((const float4*)x, (const float4*)ew);
    gate_kernel<<<NUM_TOKENS / 8, 256>>>(x, gw);

    dim3 grid(HIDDEN / 128, NUM_TOKENS / 128, NUM_EXPERTS);
    moe_hmma_kernel<<<grid, 256, SMEM_DYN>>>(out);
}

// round 5
// speedup vs baseline: 2.3566x; 1.0210x over previous
#include <cuda_runtime.h>
#include <cuda_bf16.h>
#include <cstdint>

#define NUM_EXPERTS 8
#define HIDDEN 1024
#define NUM_TOKENS 8192

// ---------------- scratch (allocation-free: __device__ globals) -------------
__device__ int   g_count[NUM_EXPERTS];
__device__ int   g_tok[NUM_EXPERTS * NUM_TOKENS];
__device__ float g_wt [NUM_EXPERTS * NUM_TOKENS];
__device__ __nv_bfloat16 g_xh [NUM_TOKENS * HIDDEN];
__device__ __nv_bfloat16 g_xl [NUM_TOKENS * HIDDEN];
__device__ __nv_bfloat16 g_ewh[NUM_EXPERTS * HIDDEN * HIDDEN];
__device__ __nv_bfloat16 g_ewl[NUM_EXPERTS * HIDDEN * HIDDEN];

// ---------------- helpers ----------------------------------------------------
__device__ __forceinline__ uint32_t smem_u32(const void* p) {
    uint32_t a;
    asm("{ .reg .u64 t; cvta.to.shared.u64 t, %1; cvt.u32.u64 %0, t; }"
        : "=r"(a) : "l"(p));
    return a;
}

__device__ __forceinline__ void cp16(uint32_t dst, const void* src) {
    asm volatile("cp.async.cg.shared.global [%0], [%1], 16;"
                 :: "r"(dst), "l"(src) : "memory");
}
__device__ __forceinline__ void cp_commit() {
    asm volatile("cp.async.commit_group;" ::: "memory");
}
template <int N>
__device__ __forceinline__ void cp_wait() {
    asm volatile("cp.async.wait_group %0;" :: "n"(N) : "memory");
}

__device__ __forceinline__ void ldsm4(uint32_t& r0, uint32_t& r1, uint32_t& r2,
                                      uint32_t& r3, uint32_t addr) {
    asm volatile("ldmatrix.sync.aligned.m8n8.x4.shared.b16 {%0,%1,%2,%3}, [%4];"
                 : "=r"(r0), "=r"(r1), "=r"(r2), "=r"(r3) : "r"(addr));
}

__device__ __forceinline__ void mma16816(float* c, const uint32_t* a,
                                         uint32_t b0, uint32_t b1) {
    asm volatile(
        "mma.sync.aligned.m16n8k16.row.col.f32.bf16.bf16.f32 "
        "{%0,%1,%2,%3}, {%4,%5,%6,%7}, {%8,%9}, {%0,%1,%2,%3};"
        : "+f"(c[0]), "+f"(c[1]), "+f"(c[2]), "+f"(c[3])
        : "r"(a[0]), "r"(a[1]), "r"(a[2]), "r"(a[3]), "r"(b0), "r"(b1));
}

__device__ __forceinline__ void split2(float a, float b, uint32_t& hi, uint32_t& lo) {
    __nv_bfloat16 ha = __float2bfloat16_rn(a);
    __nv_bfloat16 hb = __float2bfloat16_rn(b);
    __nv_bfloat16 la = __float2bfloat16_rn(a - __bfloat162float(ha));
    __nv_bfloat16 lb = __float2bfloat16_rn(b - __bfloat162float(hb));
    __nv_bfloat162 h; h.x = ha; h.y = hb;
    __nv_bfloat162 l; l.x = la; l.y = lb;
    hi = *reinterpret_cast<uint32_t*>(&h);
    lo = *reinterpret_cast<uint32_t*>(&l);
}

// ---------------- kernel 1: fused zero + counters + fp32->bf16 hi/lo --------
#define XQ (NUM_TOKENS * HIDDEN / 4)
#define EQ (NUM_EXPERTS * HIDDEN * HIDDEN / 4)
__global__ void convert_kernel(const float4* __restrict__ x4,
                               const float4* __restrict__ ew4,
                               float4* __restrict__ out4) {
    int idx = blockIdx.x * blockDim.x + threadIdx.x;
    if (idx < 8) g_count[idx] = 0;
    float4 v;
    __nv_bfloat16 *h, *l;
    if (idx < XQ) {
        out4[idx] = make_float4(0.f, 0.f, 0.f, 0.f);  // out has XQ float4s too
        v = x4[idx];
        h = g_xh + (size_t)idx * 4;
        l = g_xl + (size_t)idx * 4;
    } else {
        int j = idx - XQ;
        v = ew4[j];
        h = g_ewh + (size_t)j * 4;
        l = g_ewl + (size_t)j * 4;
    }
    uint2 H, L;
    split2(v.x, v.y, H.x, L.x);
    split2(v.z, v.w, H.y, L.y);
    *reinterpret_cast<uint2*>(h) = H;
    *reinterpret_cast<uint2*>(l) = L;
}

// ---------------- kernel 2: gating ------------------------------------------
__global__ void gate_kernel(const float* __restrict__ x,
                            const float* __restrict__ gw) {
    __shared__ float sg[NUM_EXPERTS * HIDDEN]; // 32 KB
    int tid = threadIdx.x;
    for (int i = tid; i < NUM_EXPERTS * HIDDEN; i += blockDim.x) sg[i] = gw[i];
    __syncthreads();

    int warp = tid >> 5, lane = tid & 31;
    int t = blockIdx.x * (blockDim.x >> 5) + warp;
    if (t >= NUM_TOKENS) return;

    const float* xr = x + (size_t)t * HIDDEN;
    float acc[NUM_EXPERTS];
#pragma unroll
    for (int e = 0; e < NUM_EXPERTS; e++) acc[e] = 0.f;

    for (int i = lane; i < HIDDEN; i += 32) {
        float xv = xr[i];
#pragma unroll
        for (int e = 0; e < NUM_EXPERTS; e++)
            acc[e] = fmaf(xv, sg[e * HIDDEN + i], acc[e]);
    }
#pragma unroll
    for (int e = 0; e < NUM_EXPERTS; e++) {
#pragma unroll
        for (int o = 16; o > 0; o >>= 1)
            acc[e] += __shfl_xor_sync(0xFFFFFFFFu, acc[e], o);
    }

    if (lane == 0) {
        float m = acc[0];
#pragma unroll
        for (int e = 1; e < NUM_EXPERTS; e++) m = fmaxf(m, acc[e]);
        float p[NUM_EXPERTS], s = 0.f;
#pragma unroll
        for (int e = 0; e < NUM_EXPERTS; e++) { p[e] = __expf(acc[e] - m); s += p[e]; }
        float inv = 1.f / s;
#pragma unroll
        for (int e = 0; e < NUM_EXPERTS; e++) p[e] *= inv;

        int i1 = 0;
#pragma unroll
        for (int e = 1; e < NUM_EXPERTS; e++) if (p[e] > p[i1]) i1 = e;
        int i2 = (i1 == 0) ? 1 : 0;
#pragma unroll
        for (int e = 0; e < NUM_EXPERTS; e++)
            if (e != i1 && p[e] > p[i2]) i2 = e;

        int pos1 = atomicAdd(&g_count[i1], 1);
        g_tok[i1 * NUM_TOKENS + pos1] = t;
        g_wt [i1 * NUM_TOKENS + pos1] = p[i1];
        int pos2 = atomicAdd(&g_count[i2], 1);
        g_tok[i2 * NUM_TOKENS + pos2] = t;
        g_wt [i2 * NUM_TOKENS + pos2] = p[i2];
    }
}

// ---------------- kernel 3: HMMA grouped GEMM, 4-stage cp.async -------------
// CTA: 128 tokens x 128 N, BK=16, NC=64 chunks, 4 stages, 1 sync/chunk.
// smem rows 48 B (16B-aligned; stride 12 words -> 8 rows cover all 32 banks).
#define BK    16
#define NC    (HIDDEN / BK)      // 64
#define ROWB  48
#define OFF_LO (128 * ROWB)      // 6144: hi -> lo within a side
#define OFF_B  (2 * 128 * ROWB)  // 12288: A side -> B side
#define STG   (4 * 128 * ROWB)   // 24576 bytes per stage
#define NSTAGE 4
#define SMEM_DYN (NSTAGE * STG)  // 98304

__global__ __launch_bounds__(256, 2) void moe_hmma_kernel(float* __restrict__ out) {
    int e = blockIdx.z;
    int cnt = g_count[e];
    int m0 = blockIdx.y * 128;
    if (m0 >= cnt) return;
    int n0 = blockIdx.x * 128;

    extern __shared__ __align__(16) char sm[];
    __shared__ int   s_tok[128];
    __shared__ float s_wgt[128];

    int tid = threadIdx.x, wid = tid >> 5, lane = tid & 31;
    uint32_t sb = smem_u32(sm);

    if (tid < 128) {
        int m = m0 + tid;
        int tok = -1; float wv = 0.f;
        if (m < cnt) {
            tok = g_tok[e * NUM_TOKENS + m];
            wv  = g_wt [e * NUM_TOKENS + m];
        }
        s_tok[tid] = tok;
        s_wgt[tid] = wv;
    }
    __syncthreads();

    // ---- loader mapping: 256 threads -> 128 A rows + 128 B rows -------------
    int  row = tid & 127;
    bool isB = (tid >= 128);
    const __nv_bfloat16 *hrow, *lrow;
    if (isB) {
        size_t o = ((size_t)e * HIDDEN + n0 + row) * HIDDEN;
        hrow = g_ewh + o;
        lrow = g_ewl + o;
    } else {
        int tok = s_tok[row];
        size_t o = (size_t)(tok >= 0 ? tok : 0) * HIDDEN;
        hrow = g_xh + o;
        lrow = g_xl + o;
    }
    uint32_t dst0 = sb + (isB ? OFF_B : 0) + (uint32_t)row * ROWB;

    // ---- compute mapping -----------------------------------------------------
    int warp_m = wid & 1;        // 0..1 (64 rows each)
    int warp_n = wid >> 1;       // 0..3 (32 cols each)

    uint32_t a_lane_off = (uint32_t)((lane & 15) * ROWB + (lane >> 4) * 16)
                        + (uint32_t)(warp_m * 64 * ROWB);
    uint32_t b_lane_off = (uint32_t)((((lane >> 4) * 8) + (lane & 7)) * ROWB
                                     + ((lane >> 3) & 1) * 16)
                        + OFF_B + (uint32_t)(warp_n * 32 * ROWB);

    float acc[4][4][4];
#pragma unroll
    for (int i = 0; i < 4; i++)
#pragma unroll
        for (int j = 0; j < 4; j++)
#pragma unroll
            for (int q = 0; q < 4; q++) acc[i][j][q] = 0.f;

    // ---- prologue: stage chunks 0..2 -----------------------------------------
#pragma unroll
    for (int p = 0; p < NSTAGE - 1; p++) {
        uint32_t d = dst0 + (uint32_t)(p * STG);
        const __nv_bfloat16* hp = hrow + p * BK;
        const __nv_bfloat16* lp = lrow + p * BK;
        cp16(d, hp);           cp16(d + 16, hp + 8);
        cp16(d + OFF_LO, lp);  cp16(d + OFF_LO + 16, lp + 8);
        cp_commit();
    }

    for (int c = 0; c < NC; c++) {
        // chunk c resident: groups committed = min(c+3, NC); allow pending > c
        if (c + 2 < NC)      cp_wait<2>();
        else if (c + 1 < NC) cp_wait<1>();
        else                 cp_wait<0>();
        __syncthreads();   // data visible to all; stage (c+3)%4 free of readers

        if (c + NSTAGE - 1 < NC) {
            uint32_t d = dst0 + (uint32_t)(((c + NSTAGE - 1) & (NSTAGE - 1)) * STG);
            const __nv_bfloat16* hp = hrow + (c + NSTAGE - 1) * BK;
            const __nv_bfloat16* lp = lrow + (c + NSTAGE - 1) * BK;
            cp16(d, hp);           cp16(d + 16, hp + 8);
            cp16(d + OFF_LO, lp);  cp16(d + OFF_LO + 16, lp + 8);
            cp_commit();
        }

        uint32_t stb = sb + (uint32_t)((c & (NSTAGE - 1)) * STG);
        uint32_t aH = stb + a_lane_off;
        uint32_t bH = stb + b_lane_off;

        uint32_t ah[4][4], bh[2][4];
#pragma unroll
        for (int mf = 0; mf < 4; mf++)
            ldsm4(ah[mf][0], ah[mf][1], ah[mf][2], ah[mf][3],
                  aH + mf * 16 * ROWB);
#pragma unroll
        for (int bf = 0; bf < 2; bf++)
            ldsm4(bh[bf][0], bh[bf][1], bh[bf][2], bh[bf][3],
                  bH + bf * 16 * ROWB);

        // term 1: ah * bh
#pragma unroll
        for (int mf = 0; mf < 4; mf++)
#pragma unroll
            for (int nf = 0; nf < 4; nf++)
                mma16816(acc[mf][nf], ah[mf],
                         bh[nf >> 1][(nf & 1) * 2], bh[nf >> 1][(nf & 1) * 2 + 1]);

        // term 2: al * bh
        {
            uint32_t al[4][4];
#pragma unroll
            for (int mf = 0; mf < 4; mf++)
                ldsm4(al[mf][0], al[mf][1], al[mf][2], al[mf][3],
                      aH + OFF_LO + mf * 16 * ROWB);
#pragma unroll
            for (int mf = 0; mf < 4; mf++)
#pragma unroll
                for (int nf = 0; nf < 4; nf++)
                    mma16816(acc[mf][nf], al[mf],
                             bh[nf >> 1][(nf & 1) * 2], bh[nf >> 1][(nf & 1) * 2 + 1]);
        }

        // term 3: ah * bl
        {
            uint32_t bl[2][4];
#pragma unroll
            for (int bf = 0; bf < 2; bf++)
                ldsm4(bl[bf][0], bl[bf][1], bl[bf][2], bl[bf][3],
                      bH + OFF_LO + bf * 16 * ROWB);
#pragma unroll
            for (int mf = 0; mf < 4; mf++)
#pragma unroll
                for (int nf = 0; nf < 4; nf++)
                    mma16816(acc[mf][nf], ah[mf],
                             bl[nf >> 1][(nf & 1) * 2], bl[nf >> 1][(nf & 1) * 2 + 1]);
        }
    }

    // ---- epilogue: weight-scaled float2 atomic scatter ------------------------
    int tq  = lane >> 2;
    int tc2 = (lane & 3) * 2;
#pragma unroll
    for (int mf = 0; mf < 4; mf++) {
        int r0 = warp_m * 64 + mf * 16 + tq;
        int t0 = s_tok[r0];
        int t1 = s_tok[r0 + 8];
        float w0 = s_wgt[r0];
        float w1 = s_wgt[r0 + 8];
        float* o0 = (t0 >= 0) ? out + (size_t)t0 * HIDDEN : nullptr;
        float* o1 = (t1 >= 0) ? out + (size_t)t1 * HIDDEN : nullptr;
#pragma unroll
        for (int nf = 0; nf < 4; nf++) {
            int col = n0 + warp_n * 32 + nf * 8 + tc2;
            if (o0)
                atomicAdd(reinterpret_cast<float2*>(o0 + col),
                          make_float2(w0 * acc[mf][nf][0], w0 * acc[mf][nf][1]));
            if (o1)
                atomicAdd(reinterpret_cast<float2*>(o1 + col),
                          make_float2(w1 * acc[mf][nf][2], w1 * acc[mf][nf][3]));
        }
    }
}

// ---------------- launch ------------------------------------------------------
extern "C" void kernel_launch(void* const* d_in, const int* in_sizes, int n_in,
                              void* d_out, int out_size) {
    const float* x  = (const float*)d_in[0];   // [8192,1024]
    const float* gw = (const float*)d_in[1];   // [8,1024]
    const float* ew = (const float*)d_in[2];   // [8,1024,1024]
    float* out = (float*)d_out;                // [8192,1024]

    cudaFuncSetAttribute(moe_hmma_kernel,
                         cudaFuncAttributeMaxDynamicSharedMemorySize, SMEM_DYN);

    convert_kernel<<<(XQ + EQ) / 256, 256>>>((const float4*)x, (const float4*)ew,
                                             (float4*)out);
    gate_kernel<<<NUM_TOKENS / 8, 256>>>(x, gw);

    dim3 grid(HIDDEN / 128, NUM_TOKENS / 128, NUM_EXPERTS);
    moe_hmma_kernel<<<grid, 256, SMEM_DYN>>>(out);
}

// round 6
// speedup vs baseline: 2.3864x; 1.0127x over previous
#include <cuda_runtime.h>
#include <cuda_bf16.h>
#include <cstdint>

#define NUM_EXPERTS 8
#define HIDDEN 1024
#define NUM_TOKENS 8192

// ---------------- scratch (allocation-free: __device__ globals) -------------
__device__ int   g_count[NUM_EXPERTS];
__device__ int   g_tok[NUM_EXPERTS * NUM_TOKENS];
__device__ float g_wt [NUM_EXPERTS * NUM_TOKENS];
__device__ __nv_bfloat16 g_xh [NUM_TOKENS * HIDDEN];
__device__ __nv_bfloat16 g_xl [NUM_TOKENS * HIDDEN];
__device__ __nv_bfloat16 g_ewh[NUM_EXPERTS * HIDDEN * HIDDEN];
__device__ __nv_bfloat16 g_ewl[NUM_EXPERTS * HIDDEN * HIDDEN];

// ---------------- helpers ----------------------------------------------------
__device__ __forceinline__ uint32_t smem_u32(const void* p) {
    uint32_t a;
    asm("{ .reg .u64 t; cvta.to.shared.u64 t, %1; cvt.u32.u64 %0, t; }"
        : "=r"(a) : "l"(p));
    return a;
}

__device__ __forceinline__ void cp16(uint32_t dst, const void* src) {
    asm volatile("cp.async.cg.shared.global [%0], [%1], 16;"
                 :: "r"(dst), "l"(src) : "memory");
}
__device__ __forceinline__ void cp_commit() {
    asm volatile("cp.async.commit_group;" ::: "memory");
}
template <int N>
__device__ __forceinline__ void cp_wait() {
    asm volatile("cp.async.wait_group %0;" :: "n"(N) : "memory");
}

__device__ __forceinline__ void ldsm4(uint32_t& r0, uint32_t& r1, uint32_t& r2,
                                      uint32_t& r3, uint32_t addr) {
    asm volatile("ldmatrix.sync.aligned.m8n8.x4.shared.b16 {%0,%1,%2,%3}, [%4];"
                 : "=r"(r0), "=r"(r1), "=r"(r2), "=r"(r3) : "r"(addr));
}

__device__ __forceinline__ void mma16816(float* c, const uint32_t* a,
                                         uint32_t b0, uint32_t b1) {
    asm volatile(
        "mma.sync.aligned.m16n8k16.row.col.f32.bf16.bf16.f32 "
        "{%0,%1,%2,%3}, {%4,%5,%6,%7}, {%8,%9}, {%0,%1,%2,%3};"
        : "+f"(c[0]), "+f"(c[1]), "+f"(c[2]), "+f"(c[3])
        : "r"(a[0]), "r"(a[1]), "r"(a[2]), "r"(a[3]), "r"(b0), "r"(b1));
}

__device__ __forceinline__ void split2(float a, float b, uint32_t& hi, uint32_t& lo) {
    __nv_bfloat16 ha = __float2bfloat16_rn(a);
    __nv_bfloat16 hb = __float2bfloat16_rn(b);
    __nv_bfloat16 la = __float2bfloat16_rn(a - __bfloat162float(ha));
    __nv_bfloat16 lb = __float2bfloat16_rn(b - __bfloat162float(hb));
    __nv_bfloat162 h; h.x = ha; h.y = hb;
    __nv_bfloat162 l; l.x = la; l.y = lb;
    hi = *reinterpret_cast<uint32_t*>(&h);
    lo = *reinterpret_cast<uint32_t*>(&l);
}

// ---------------- kernel 1: fused prep (zero + convert + gate) --------------
#define XQ (NUM_TOKENS * HIDDEN / 4)
#define EQ (NUM_EXPERTS * HIDDEN * HIDDEN / 4)
#define NB_CONV ((XQ + EQ) / 256)
#define NB_GATE (NUM_TOKENS / 8)

__global__ void prep_kernel(const float4* __restrict__ x4,
                            const float4* __restrict__ ew4,
                            float4* __restrict__ out4,
                            const float* __restrict__ x,
                            const float* __restrict__ gw) {
    __shared__ float sg[NUM_EXPERTS * HIDDEN]; // 32 KB (gate blocks only)
    int tid = threadIdx.x;

    if (blockIdx.x < NB_CONV) {
        // ---------------- convert + zero part --------------------------------
        int idx = blockIdx.x * 256 + tid;
        if (idx < 8) g_count[idx] = 0;
        float4 v;
        __nv_bfloat16 *h, *l;
        if (idx < XQ) {
            out4[idx] = make_float4(0.f, 0.f, 0.f, 0.f);
            v = x4[idx];
            h = g_xh + (size_t)idx * 4;
            l = g_xl + (size_t)idx * 4;
        } else {
            int j = idx - XQ;
            v = ew4[j];
            h = g_ewh + (size_t)j * 4;
            l = g_ewl + (size_t)j * 4;
        }
        uint2 H, L;
        split2(v.x, v.y, H.x, L.x);
        split2(v.z, v.w, H.y, L.y);
        *reinterpret_cast<uint2*>(h) = H;
        *reinterpret_cast<uint2*>(l) = L;
        return;
    }

    // ---------------- gate part ----------------------------------------------
    int gbid = blockIdx.x - NB_CONV;
    for (int i = tid; i < NUM_EXPERTS * HIDDEN; i += 256) sg[i] = gw[i];
    __syncthreads();

    int warp = tid >> 5, lane = tid & 31;
    int t = gbid * 8 + warp;
    if (t >= NUM_TOKENS) return;

    const float* xr = x + (size_t)t * HIDDEN;
    float acc[NUM_EXPERTS];
#pragma unroll
    for (int e = 0; e < NUM_EXPERTS; e++) acc[e] = 0.f;

    for (int i = lane; i < HIDDEN; i += 32) {
        float xv = xr[i];
#pragma unroll
        for (int e = 0; e < NUM_EXPERTS; e++)
            acc[e] = fmaf(xv, sg[e * HIDDEN + i], acc[e]);
    }
#pragma unroll
    for (int e = 0; e < NUM_EXPERTS; e++) {
#pragma unroll
        for (int o = 16; o > 0; o >>= 1)
            acc[e] += __shfl_xor_sync(0xFFFFFFFFu, acc[e], o);
    }

    if (lane == 0) {
        float m = acc[0];
#pragma unroll
        for (int e = 1; e < NUM_EXPERTS; e++) m = fmaxf(m, acc[e]);
        float p[NUM_EXPERTS], s = 0.f;
#pragma unroll
        for (int e = 0; e < NUM_EXPERTS; e++) { p[e] = __expf(acc[e] - m); s += p[e]; }
        float inv = 1.f / s;
#pragma unroll
        for (int e = 0; e < NUM_EXPERTS; e++) p[e] *= inv;

        int i1 = 0;
#pragma unroll
        for (int e = 1; e < NUM_EXPERTS; e++) if (p[e] > p[i1]) i1 = e;
        int i2 = (i1 == 0) ? 1 : 0;
#pragma unroll
        for (int e = 0; e < NUM_EXPERTS; e++)
            if (e != i1 && p[e] > p[i2]) i2 = e;

        int pos1 = atomicAdd(&g_count[i1], 1);
        g_tok[i1 * NUM_TOKENS + pos1] = t;
        g_wt [i1 * NUM_TOKENS + pos1] = p[i1];
        int pos2 = atomicAdd(&g_count[i2], 1);
        g_tok[i2 * NUM_TOKENS + pos2] = t;
        g_wt [i2 * NUM_TOKENS + pos2] = p[i2];
    }
}

// ---------------- kernel 2: HMMA grouped GEMM, BK=32, 1 sync/chunk ----------
// CTA: 128 tokens x 128 N. 8 warps in 2(M) x 4(N). 2 stages.
// smem rows padded to 80 B -> conflict-free ldmatrix/cp.async.
#define BK    32
#define NC    (HIDDEN / BK)      // 32 chunks -> 32 barriers total
#define ROWB  80
#define OFF_LO (128 * ROWB)      // 10240: hi -> lo within a side
#define OFF_B  (2 * 128 * ROWB)  // 20480: A side -> B side
#define STG   (4 * 128 * ROWB)   // 40960 bytes per stage
#define SMEM_DYN (2 * STG)       // 81920

__global__ __launch_bounds__(256, 2) void moe_hmma_kernel(float* __restrict__ out) {
    int e = blockIdx.z;
    int cnt = g_count[e];
    int m0 = blockIdx.y * 128;
    if (m0 >= cnt) return;
    int n0 = blockIdx.x * 128;

    extern __shared__ __align__(16) char sm[];
    __shared__ int   s_tok[128];
    __shared__ float s_wgt[128];

    int tid = threadIdx.x, wid = tid >> 5, lane = tid & 31;
    uint32_t sb = smem_u32(sm);

    if (tid < 128) {
        int m = m0 + tid;
        int tok = -1; float wv = 0.f;
        if (m < cnt) {
            tok = g_tok[e * NUM_TOKENS + m];
            wv  = g_wt [e * NUM_TOKENS + m];
        }
        s_tok[tid] = tok;
        s_wgt[tid] = wv;
    }
    __syncthreads();

    // ---- loader mapping: 256 threads -> 128 A rows + 128 B rows -------------
    int  row = tid & 127;
    bool isB = (tid >= 128);
    const __nv_bfloat16 *hrow, *lrow;
    if (isB) {
        size_t o = ((size_t)e * HIDDEN + n0 + row) * HIDDEN;
        hrow = g_ewh + o;
        lrow = g_ewl + o;
    } else {
        int tok = s_tok[row];
        size_t o = (size_t)(tok >= 0 ? tok : 0) * HIDDEN;
        hrow = g_xh + o;
        lrow = g_xl + o;
    }
    uint32_t dst0 = sb + (isB ? OFF_B : 0) + (uint32_t)row * ROWB;

    // ---- compute mapping -----------------------------------------------------
    int warp_m = wid & 1;        // 0..1 (64 rows each)
    int warp_n = wid >> 1;       // 0..3 (32 cols each)

    uint32_t a_lane_off = (uint32_t)((lane & 15) * ROWB + (lane >> 4) * 16)
                        + (uint32_t)(warp_m * 64 * ROWB);
    uint32_t b_lane_off = (uint32_t)((((lane >> 4) * 8) + (lane & 7)) * ROWB
                                     + ((lane >> 3) & 1) * 16)
                        + OFF_B + (uint32_t)(warp_n * 32 * ROWB);

    float acc[4][4][4];
#pragma unroll
    for (int i = 0; i < 4; i++)
#pragma unroll
        for (int j = 0; j < 4; j++)
#pragma unroll
            for (int q = 0; q < 4; q++) acc[i][j][q] = 0.f;

    // ---- prologue: stage chunk 0 into stage 0 ---------------------------------
    {
        const __nv_bfloat16* hp = hrow;
        const __nv_bfloat16* lp = lrow;
#pragma unroll
        for (int j = 0; j < 4; j++) cp16(dst0 + j * 16, hp + j * 8);
#pragma unroll
        for (int j = 0; j < 4; j++) cp16(dst0 + OFF_LO + j * 16, lp + j * 8);
        cp_commit();
    }

    for (int c = 0; c < NC; c++) {
        cp_wait<0>();      // chunk c fully resident (this thread's copies)
        __syncthreads();   // all threads' copies visible; prior stage free

        if (c + 1 < NC) {  // prefetch chunk c+1 into the other stage
            uint32_t d = dst0 + (uint32_t)(((c + 1) & 1) * STG);
            const __nv_bfloat16* hp = hrow + (c + 1) * BK;
            const __nv_bfloat16* lp = lrow + (c + 1) * BK;
#pragma unroll
            for (int j = 0; j < 4; j++) cp16(d + j * 16, hp + j * 8);
#pragma unroll
            for (int j = 0; j < 4; j++) cp16(d + OFF_LO + j * 16, lp + j * 8);
            cp_commit();
        }

        uint32_t stb = sb + (uint32_t)((c & 1) * STG);
        uint32_t aH = stb + a_lane_off;
        uint32_t bH = stb + b_lane_off;

#pragma unroll
        for (int ks = 0; ks < 2; ks++) {
            uint32_t ko = (uint32_t)(ks * 32);  // 16 bf16 = 32 B

            uint32_t ah[4][4], bh[2][4];
#pragma unroll
            for (int mf = 0; mf < 4; mf++)
                ldsm4(ah[mf][0], ah[mf][1], ah[mf][2], ah[mf][3],
                      aH + mf * 16 * ROWB + ko);
#pragma unroll
            for (int bf = 0; bf < 2; bf++)
                ldsm4(bh[bf][0], bh[bf][1], bh[bf][2], bh[bf][3],
                      bH + bf * 16 * ROWB + ko);

            // term 1: ah * bh
#pragma unroll
            for (int mf = 0; mf < 4; mf++)
#pragma unroll
                for (int nf = 0; nf < 4; nf++)
                    mma16816(acc[mf][nf], ah[mf],
                             bh[nf >> 1][(nf & 1) * 2], bh[nf >> 1][(nf & 1) * 2 + 1]);

            // term 2: al * bh
            {
                uint32_t al[4][4];
#pragma unroll
                for (int mf = 0; mf < 4; mf++)
                    ldsm4(al[mf][0], al[mf][1], al[mf][2], al[mf][3],
                          aH + OFF_LO + mf * 16 * ROWB + ko);
#pragma unroll
                for (int mf = 0; mf < 4; mf++)
#pragma unroll
                    for (int nf = 0; nf < 4; nf++)
                        mma16816(acc[mf][nf], al[mf],
                                 bh[nf >> 1][(nf & 1) * 2], bh[nf >> 1][(nf & 1) * 2 + 1]);
            }

            // term 3: ah * bl
            {
                uint32_t bl[2][4];
#pragma unroll
                for (int bf = 0; bf < 2; bf++)
                    ldsm4(bl[bf][0], bl[bf][1], bl[bf][2], bl[bf][3],
                          bH + OFF_LO + bf * 16 * ROWB + ko);
#pragma unroll
                for (int mf = 0; mf < 4; mf++)
#pragma unroll
                    for (int nf = 0; nf < 4; nf++)
                        mma16816(acc[mf][nf], ah[mf],
                                 bl[nf >> 1][(nf & 1) * 2], bl[nf >> 1][(nf & 1) * 2 + 1]);
            }
        }
    }

    // ---- epilogue: weight-scaled float2 atomic scatter ------------------------
    int tq  = lane >> 2;
    int tc2 = (lane & 3) * 2;
#pragma unroll
    for (int mf = 0; mf < 4; mf++) {
        int r0 = warp_m * 64 + mf * 16 + tq;
        int t0 = s_tok[r0];
        int t1 = s_tok[r0 + 8];
        float w0 = s_wgt[r0];
        float w1 = s_wgt[r0 + 8];
        float* o0 = (t0 >= 0) ? out + (size_t)t0 * HIDDEN : nullptr;
        float* o1 = (t1 >= 0) ? out + (size_t)t1 * HIDDEN : nullptr;
#pragma unroll
        for (int nf = 0; nf < 4; nf++) {
            int col = n0 + warp_n * 32 + nf * 8 + tc2;
            if (o0)
                atomicAdd(reinterpret_cast<float2*>(o0 + col),
                          make_float2(w0 * acc[mf][nf][0], w0 * acc[mf][nf][1]));
            if (o1)
                atomicAdd(reinterpret_cast<float2*>(o1 + col),
                          make_float2(w1 * acc[mf][nf][2], w1 * acc[mf][nf][3]));
        }
    }
}

// ---------------- launch ------------------------------------------------------
extern "C" void kernel_launch(void* const* d_in, const int* in_sizes, int n_in,
                              void* d_out, int out_size) {
    const float* x  = (const float*)d_in[0];   // [8192,1024]
    const float* gw = (const float*)d_in[1];   // [8,1024]
    const float* ew = (const float*)d_in[2];   // [8,1024,1024]
    float* out = (float*)d_out;                // [8192,1024]

    cudaFuncSetAttribute(moe_hmma_kernel,
                         cudaFuncAttributeMaxDynamicSharedMemorySize, SMEM_DYN);

    prep_kernel<<<NB_CONV + NB_GATE, 256>>>((const float4*)x, (const float4*)ew,
                                            (float4*)out, x, gw);

    dim3 grid(HIDDEN / 128, NUM_TOKENS / 128, NUM_EXPERTS);
    moe_hmma_kernel<<<grid, 256, SMEM_DYN>>>(out);
}